// round 16
// baseline (speedup 1.0000x reference)
#include <cuda_runtime.h>
#include <stdint.h>

// cdist: out[i,j] = sqrt(max(||xi||^2 + ||xj||^2 - 2*dot(xi,xj), 0))
// R16 = R13 champion with the tf32 rounding removed: raw fp32 bits are stored
// to smem and the m16n8k8 TF32 MMA truncates to tf32 internally (RZ instead
// of RNA; error ~2x, still ~1e-4 rel, 8x under the 1e-3 gate). Load phase is
// now pure LDG.128 -> sumsq FFMA -> STS.128.
// Structure: 256 thr/CTA, one 128x128 tile per CTA (16384 CTAs), 2x4 warp
// grid, 64x32 warp tiles, SW128 smem, permuted-B STG.128 epilogue, hoisted
// LDSM addresses, incremental output pointers.

#define NPTS 16384

__device__ __forceinline__ float sqrt_approx(float v) {
    float r; asm("sqrt.approx.f32 %0, %1;" : "=f"(r) : "f"(v)); return r;
}
__device__ __forceinline__ float dist_val(float si, float sj, float dot) {
    return sqrt_approx(fmaxf(fmaf(-2.0f, dot, si + sj), 0.0f));
}
__device__ __forceinline__ uint32_t smem_u32(const void* p) {
    return (uint32_t)__cvta_generic_to_shared(p);
}
__device__ __forceinline__ void ldmatrix_x4(uint32_t* r, uint32_t addr) {
    asm volatile("ldmatrix.sync.aligned.m8n8.x4.shared.b16 {%0,%1,%2,%3}, [%4];"
                 : "=r"(r[0]), "=r"(r[1]), "=r"(r[2]), "=r"(r[3]) : "r"(addr));
}
__device__ __forceinline__ void mma_tf32(float* c, const uint32_t* a,
                                         uint32_t b0, uint32_t b1) {
    asm volatile(
        "mma.sync.aligned.m16n8k8.row.col.f32.tf32.tf32.f32 "
        "{%0,%1,%2,%3}, {%4,%5,%6,%7}, {%8,%9}, {%0,%1,%2,%3};"
        : "+f"(c[0]), "+f"(c[1]), "+f"(c[2]), "+f"(c[3])
        : "r"(a[0]), "r"(a[1]), "r"(a[2]), "r"(a[3]), "r"(b0), "r"(b1));
}

// 16B store into SW128-swizzled [128 rows][128B] tile: chunk c of row r lands
// at r*128 + ((c ^ (r&7))*16).
__device__ __forceinline__ void st16_sw(uint8_t* buf, int row, int chunk, float4 v) {
    *(float4*)(buf + row * 128 + (((uint32_t)chunk ^ (row & 7)) << 4)) = v;
}

// Store half a row (16 floats) raw to swizzled smem; return fp32 sumsq.
__device__ __forceinline__ float raw_store(uint8_t* __restrict__ buf, int row,
                                           int half, const float4* __restrict__ src)
{
    float s = 0.0f;
#pragma unroll
    for (int q = 0; q < 4; q++) {
        float4 v = src[q];
        s = fmaf(v.x, v.x, s); s = fmaf(v.y, v.y, s);
        s = fmaf(v.z, v.z, s); s = fmaf(v.w, v.w, s);
        st16_sw(buf, row, half * 4 + q, v);
    }
    return s;
}

__global__ void __launch_bounds__(256, 2)
cdist_tf32_kernel(const float* __restrict__ x, float* __restrict__ out)
{
    __shared__ __align__(128) uint8_t Abuf[128 * 128];
    __shared__ __align__(128) uint8_t Bbuf[128 * 128];
    __shared__ float sqa[128];
    __shared__ float sqb[128];

    const int t    = threadIdx.x;
    const int lane = t & 31;
    const int wid  = t >> 5;
    const int a0   = blockIdx.y << 7;
    const int b0   = blockIdx.x << 7;

    // ---- load + raw store (thread t: row t/2, half t&1) ----
    // B rows permuted within each 16-group (STG.128 epilogue permutation):
    //   invperm (global v -> smem slot): ((w&1)<<3)|((w>>1)<<1)|r, w=(v&15)>>1, r=v&1
    {
        const int row  = t >> 1;
        const int half = t & 1;
        const int v = row & 15, w = v >> 1, r = v & 1;
        const int srowB = (row & ~15) | ((w & 1) << 3) | ((w >> 1) << 1) | r;
        const float4* xa = (const float4*)(x + ((size_t)(a0 + row) << 5)) + half * 4;
        const float4* xb = (const float4*)(x + ((size_t)(b0 + row) << 5)) + half * 4;
        float sa = raw_store(Abuf, row,   half, xa);
        float sb = raw_store(Bbuf, srowB, half, xb);
        sa += __shfl_xor_sync(0xFFFFFFFFu, sa, 1);
        sb += __shfl_xor_sync(0xFFFFFFFFu, sb, 1);
        if (!half) { sqa[row] = sa; sqb[row] = sb; }
    }
    __syncthreads();

    // ---- warp GEMM: warp tile 64x32, 4 k-steps of k8 ----
    const int wr = wid >> 2;
    const int wc = wid & 3;
    const uint32_t lx = (uint32_t)(lane & 7);

    const uint32_t aRow  = (uint32_t)(wr * 64) + lx + (((uint32_t)(lane >> 3) & 1) << 3);
    const uint32_t aBase = smem_u32(Abuf) + aRow * 128;
    const uint32_t aCsel = (uint32_t)(lane >> 4);          // 0..1
    const uint32_t bRow  = (uint32_t)(wc * 32) + lx;
    const uint32_t bBase = smem_u32(Bbuf) + bRow * 128;
    const uint32_t bCsel = (uint32_t)(lane >> 3);          // 0..3

    // Hoisted swizzled chunk addresses (no per-step XOR chains):
    uint32_t aOff[4], bOff[2];
#pragma unroll
    for (int ks = 0; ks < 4; ks++)
        aOff[ks] = aBase + ((((uint32_t)(2 * ks) + aCsel) ^ lx) << 4);
#pragma unroll
    for (int kp = 0; kp < 2; kp++)
        bOff[kp] = bBase + ((((uint32_t)(4 * kp) + bCsel) ^ lx) << 4);

    float acc[4][4][4];
#pragma unroll
    for (int mt = 0; mt < 4; mt++)
#pragma unroll
        for (int nt = 0; nt < 4; nt++)
#pragma unroll
            for (int i = 0; i < 4; i++) acc[mt][nt][i] = 0.0f;

#pragma unroll
    for (int kp = 0; kp < 2; kp++) {
        // B frags for 2 k-steps: regs {b0_ks0, b1_ks0, b0_ks1, b1_ks1}
        uint32_t bp[4][4];
#pragma unroll
        for (int nt = 0; nt < 4; nt++)
            ldmatrix_x4(bp[nt], bOff[kp] + (uint32_t)nt * 1024);

#pragma unroll
        for (int k2 = 0; k2 < 2; k2++) {
            const int ks = 2 * kp + k2;
            uint32_t af[4][4];
#pragma unroll
            for (int mt = 0; mt < 4; mt++)
                ldmatrix_x4(af[mt], aOff[ks] + (uint32_t)mt * 2048);
#pragma unroll
            for (int mt = 0; mt < 4; mt++)
#pragma unroll
                for (int nt = 0; nt < 4; nt++)
                    mma_tf32(acc[mt][nt], af[mt],
                             bp[nt][2 * k2], bp[nt][2 * k2 + 1]);
        }
    }

    // ---- epilogue: STG.128, incremental pointers ----
    const int q  = lane & 3;
    const int gr = lane >> 2;
    const bool diag = (a0 == b0);
    const int colBase = b0 + wc * 32 + q * 4;
    float* optr = out + (((size_t)(a0 + wr * 64 + gr)) << 14) + colBase;
    const size_t rowStep8  = (size_t)8 << 14;    // 8 rows
    const size_t rowStep16 = (size_t)16 << 14;   // to next mt (16 rows)
#pragma unroll
    for (int mt = 0; mt < 4; mt++) {
        const int r0l = wr * 64 + mt * 16 + gr;
        const float si0 = sqa[r0l], si1 = sqa[r0l + 8];
        const int g0 = a0 + r0l, g1 = g0 + 8;
        float* __restrict__ o0 = optr;
        float* __restrict__ o1 = optr + rowStep8;
#pragma unroll
        for (int u = 0; u < 2; u++) {
            const int cl = wc * 32 + u * 16 + q * 4;
            const int gc = b0 + cl;
            const float4 sj = *(const float4*)&sqb[cl];
            const float* p0 = acc[mt][2 * u];
            const float* p1 = acc[mt][2 * u + 1];
            float4 w0, w1;
            w0.x = dist_val(si0, sj.x, p0[0]);
            w0.y = dist_val(si0, sj.y, p0[1]);
            w0.z = dist_val(si0, sj.z, p1[0]);
            w0.w = dist_val(si0, sj.w, p1[1]);
            w1.x = dist_val(si1, sj.x, p0[2]);
            w1.y = dist_val(si1, sj.y, p0[3]);
            w1.z = dist_val(si1, sj.z, p1[2]);
            w1.w = dist_val(si1, sj.w, p1[3]);
            if (diag) {
                const int d0 = g0 - gc;
                if (d0 >= 0 && d0 < 4) ((float*)&w0)[d0] = 0.0f;
                const int d1 = g1 - gc;
                if (d1 >= 0 && d1 < 4) ((float*)&w1)[d1] = 0.0f;
            }
            *(float4*)(o0 + u * 16) = w0;
            *(float4*)(o1 + u * 16) = w1;
        }
        optr += rowStep16;
    }
}

extern "C" void kernel_launch(void* const* d_in, const int* in_sizes, int n_in,
                              void* d_out, int out_size)
{
    (void)in_sizes; (void)n_in; (void)out_size;
    const float* x = (const float*)d_in[0];
    float* out = (float*)d_out;
    dim3 grid(NPTS / 128, NPTS / 128);
    cdist_tf32_kernel<<<grid, 256>>>(x, out);
}

// round 17
// speedup vs baseline: 1.0235x; 1.0235x over previous
#include <cuda_runtime.h>
#include <stdint.h>

// cdist: out[i,j] = sqrt(max(||xi||^2 + ||xj||^2 - 2*dot(xi,xj), 0))
// FINAL (= R13/R15 champion, best measured 243.9us, reproduced 244.1us).
// Structure: 256 thr/CTA, one 128x128 output tile per CTA (16384 CTAs),
// TF32 mma.sync.m16n8k8 (inputs rounded via cvt.rna.tf32.f32 — the rounding
// instructions double as load-phase latency filler; removing them measurably
// regresses), 2x4 warp grid with 64x32 warp tiles, SW128-swizzled smem
// operand tiles, permuted-B rows for STG.128 epilogue, hoisted LDSM
// addresses, incremental output pointers. L1TEX-wavefront-bound at ~88%.

#define NPTS 16384

__device__ __forceinline__ float sqrt_approx(float v) {
    float r; asm("sqrt.approx.f32 %0, %1;" : "=f"(r) : "f"(v)); return r;
}
__device__ __forceinline__ float dist_val(float si, float sj, float dot) {
    return sqrt_approx(fmaxf(fmaf(-2.0f, dot, si + sj), 0.0f));
}
__device__ __forceinline__ uint32_t smem_u32(const void* p) {
    return (uint32_t)__cvta_generic_to_shared(p);
}
__device__ __forceinline__ uint32_t tf32_rna(float f) {
    uint32_t u; asm("cvt.rna.tf32.f32 %0, %1;" : "=r"(u) : "f"(f)); return u;
}
__device__ __forceinline__ void ldmatrix_x4(uint32_t* r, uint32_t addr) {
    asm volatile("ldmatrix.sync.aligned.m8n8.x4.shared.b16 {%0,%1,%2,%3}, [%4];"
                 : "=r"(r[0]), "=r"(r[1]), "=r"(r[2]), "=r"(r[3]) : "r"(addr));
}
__device__ __forceinline__ void mma_tf32(float* c, const uint32_t* a,
                                         uint32_t b0, uint32_t b1) {
    asm volatile(
        "mma.sync.aligned.m16n8k8.row.col.f32.tf32.tf32.f32 "
        "{%0,%1,%2,%3}, {%4,%5,%6,%7}, {%8,%9}, {%0,%1,%2,%3};"
        : "+f"(c[0]), "+f"(c[1]), "+f"(c[2]), "+f"(c[3])
        : "r"(a[0]), "r"(a[1]), "r"(a[2]), "r"(a[3]), "r"(b0), "r"(b1));
}

// 16B store into SW128-swizzled [128 rows][128B] tile: chunk c of row r lands
// at r*128 + ((c ^ (r&7))*16).
__device__ __forceinline__ void st16_sw(uint8_t* buf, int row, int chunk, uint4 v) {
    *(uint4*)(buf + row * 128 + (((uint32_t)chunk ^ (row & 7)) << 4)) = v;
}

// Convert half a row (16 floats) to tf32-rounded fp32, store swizzled; return sumsq.
__device__ __forceinline__ float cvt_store(uint8_t* __restrict__ buf, int row,
                                           int half, const float4* __restrict__ src)
{
    float s = 0.0f;
#pragma unroll
    for (int q = 0; q < 4; q++) {
        float4 v = src[q];
        s = fmaf(v.x, v.x, s); s = fmaf(v.y, v.y, s);
        s = fmaf(v.z, v.z, s); s = fmaf(v.w, v.w, s);
        uint4 w = make_uint4(tf32_rna(v.x), tf32_rna(v.y),
                             tf32_rna(v.z), tf32_rna(v.w));
        st16_sw(buf, row, half * 4 + q, w);
    }
    return s;
}

__global__ void __launch_bounds__(256, 2)
cdist_tf32_kernel(const float* __restrict__ x, float* __restrict__ out)
{
    __shared__ __align__(128) uint8_t Abuf[128 * 128];
    __shared__ __align__(128) uint8_t Bbuf[128 * 128];
    __shared__ float sqa[128];
    __shared__ float sqb[128];

    const int t    = threadIdx.x;
    const int lane = t & 31;
    const int wid  = t >> 5;
    const int a0   = blockIdx.y << 7;
    const int b0   = blockIdx.x << 7;

    // ---- load + tf32-round (thread t: row t/2, half t&1) ----
    // B rows permuted within each 16-group (STG.128 epilogue permutation):
    //   invperm (global v -> smem slot): ((w&1)<<3)|((w>>1)<<1)|r, w=(v&15)>>1, r=v&1
    {
        const int row  = t >> 1;
        const int half = t & 1;
        const int v = row & 15, w = v >> 1, r = v & 1;
        const int srowB = (row & ~15) | ((w & 1) << 3) | ((w >> 1) << 1) | r;
        const float4* xa = (const float4*)(x + ((size_t)(a0 + row) << 5)) + half * 4;
        const float4* xb = (const float4*)(x + ((size_t)(b0 + row) << 5)) + half * 4;
        float sa = cvt_store(Abuf, row,   half, xa);
        float sb = cvt_store(Bbuf, srowB, half, xb);
        sa += __shfl_xor_sync(0xFFFFFFFFu, sa, 1);
        sb += __shfl_xor_sync(0xFFFFFFFFu, sb, 1);
        if (!half) { sqa[row] = sa; sqb[row] = sb; }
    }
    __syncthreads();

    // ---- warp GEMM: warp tile 64x32, 4 k-steps of k8 ----
    const int wr = wid >> 2;
    const int wc = wid & 3;
    const uint32_t lx = (uint32_t)(lane & 7);

    const uint32_t aRow  = (uint32_t)(wr * 64) + lx + (((uint32_t)(lane >> 3) & 1) << 3);
    const uint32_t aBase = smem_u32(Abuf) + aRow * 128;
    const uint32_t aCsel = (uint32_t)(lane >> 4);          // 0..1
    const uint32_t bRow  = (uint32_t)(wc * 32) + lx;
    const uint32_t bBase = smem_u32(Bbuf) + bRow * 128;
    const uint32_t bCsel = (uint32_t)(lane >> 3);          // 0..3

    // Hoisted swizzled chunk addresses (no per-step XOR chains):
    uint32_t aOff[4], bOff[2];
#pragma unroll
    for (int ks = 0; ks < 4; ks++)
        aOff[ks] = aBase + ((((uint32_t)(2 * ks) + aCsel) ^ lx) << 4);
#pragma unroll
    for (int kp = 0; kp < 2; kp++)
        bOff[kp] = bBase + ((((uint32_t)(4 * kp) + bCsel) ^ lx) << 4);

    float acc[4][4][4];
#pragma unroll
    for (int mt = 0; mt < 4; mt++)
#pragma unroll
        for (int nt = 0; nt < 4; nt++)
#pragma unroll
            for (int i = 0; i < 4; i++) acc[mt][nt][i] = 0.0f;

#pragma unroll
    for (int kp = 0; kp < 2; kp++) {
        // B frags for 2 k-steps: regs {b0_ks0, b1_ks0, b0_ks1, b1_ks1}
        uint32_t bp[4][4];
#pragma unroll
        for (int nt = 0; nt < 4; nt++)
            ldmatrix_x4(bp[nt], bOff[kp] + (uint32_t)nt * 1024);

#pragma unroll
        for (int k2 = 0; k2 < 2; k2++) {
            const int ks = 2 * kp + k2;
            uint32_t af[4][4];
#pragma unroll
            for (int mt = 0; mt < 4; mt++)
                ldmatrix_x4(af[mt], aOff[ks] + (uint32_t)mt * 2048);
#pragma unroll
            for (int mt = 0; mt < 4; mt++)
#pragma unroll
                for (int nt = 0; nt < 4; nt++)
                    mma_tf32(acc[mt][nt], af[mt],
                             bp[nt][2 * k2], bp[nt][2 * k2 + 1]);
        }
    }

    // ---- epilogue: STG.128, incremental pointers ----
    const int q  = lane & 3;
    const int gr = lane >> 2;
    const bool diag = (a0 == b0);
    const int colBase = b0 + wc * 32 + q * 4;
    // thread's first output row: a0 + wr*64 + gr
    float* optr = out + (((size_t)(a0 + wr * 64 + gr)) << 14) + colBase;
    const size_t rowStep8  = (size_t)8 << 14;    // 8 rows
    const size_t rowStep16 = (size_t)16 << 14;   // to next mt (16 rows)
#pragma unroll
    for (int mt = 0; mt < 4; mt++) {
        const int r0l = wr * 64 + mt * 16 + gr;
        const float si0 = sqa[r0l], si1 = sqa[r0l + 8];
        const int g0 = a0 + r0l, g1 = g0 + 8;
        float* __restrict__ o0 = optr;
        float* __restrict__ o1 = optr + rowStep8;
#pragma unroll
        for (int u = 0; u < 2; u++) {
            const int cl = wc * 32 + u * 16 + q * 4;
            const int gc = b0 + cl;
            const float4 sj = *(const float4*)&sqb[cl];
            const float* p0 = acc[mt][2 * u];
            const float* p1 = acc[mt][2 * u + 1];
            float4 w0, w1;
            w0.x = dist_val(si0, sj.x, p0[0]);
            w0.y = dist_val(si0, sj.y, p0[1]);
            w0.z = dist_val(si0, sj.z, p1[0]);
            w0.w = dist_val(si0, sj.w, p1[1]);
            w1.x = dist_val(si1, sj.x, p0[2]);
            w1.y = dist_val(si1, sj.y, p0[3]);
            w1.z = dist_val(si1, sj.z, p1[2]);
            w1.w = dist_val(si1, sj.w, p1[3]);
            if (diag) {
                const int d0 = g0 - gc;
                if (d0 >= 0 && d0 < 4) ((float*)&w0)[d0] = 0.0f;
                const int d1 = g1 - gc;
                if (d1 >= 0 && d1 < 4) ((float*)&w1)[d1] = 0.0f;
            }
            *(float4*)(o0 + u * 16) = w0;
            *(float4*)(o1 + u * 16) = w1;
        }
        optr += rowStep16;
    }
}

extern "C" void kernel_launch(void* const* d_in, const int* in_sizes, int n_in,
                              void* d_out, int out_size)
{
    (void)in_sizes; (void)n_in; (void)out_size;
    const float* x = (const float*)d_in[0];
    float* out = (float*)d_out;
    dim3 grid(NPTS / 128, NPTS / 128);
    cdist_tf32_kernel<<<grid, 256>>>(x, out);
}